// round 15
// baseline (speedup 1.0000x reference)
#include <cuda_runtime.h>

#define NEVT    400000
#define NLOCS   100000
#define NTIMES  168
#define NKEYS   (NLOCS * NTIMES)          /* 16,800,000 */
#define NWORDS  (NKEYS / 4)               /* 4,200,000 packed counter words */
#define OUTC    256
#define SCAN_T  256
#define WPB     4096
#define NSBLK   ((NWORDS + WPB - 1) / WPB)/* 1026 */
#define HB      ((NEVT + 255) / 256)      /* 1563 */
#define NTILES  (NLOCS / 32)              /* 3125 P1 tiles (32 rows) */
#define T1      1042
#define T2      1042
#define T3      1041
#define RPB     256                       /* rows per k4 block (8 warps x 32) */
#define FB      ((NEVT + RPB - 1) / RPB)  /* 1563 final blocks */
#define CB      ((NEVT + 255) / 256)      /* cleanup blocks (ride k4 grid) */
#define AGMASK  0x3FFFFFFFFFFFFFFFull

typedef unsigned int u32;
typedef unsigned long long u64;

// ---------------- scratch ----------------
__device__ u32 g_cntw[NWORDS];
__device__ u32 g_rowid[NKEYS];
__device__ u64 g_state[NSBLK];
__device__ u32 g_numrows;
__device__ u32 g_key[NEVT];
__device__ u32 g_count[NEVT];
__device__ u32 g_cursor[NEVT];
__device__ u32 g_evtu[NEVT];
__device__ __align__(16) float g_P1[(size_t)NLOCS * OUTC];
__device__ __align__(16) float g_P2b[NTIMES * OUTC];
__device__ __align__(16) float g_P3[NTIMES * OUTC];

// ---------------- helpers ----------------
__device__ __forceinline__ u64 ffma2(u64 a, u64 b, u64 c) {
    u64 d;
    asm("fma.rn.f32x2 %0, %1, %2, %3;" : "=l"(d) : "l"(a), "l"(b), "l"(c));
    return d;
}
__device__ __forceinline__ u64 pack2(float lo, float hi) {
    u64 r;
    asm("mov.b64 %0, {%1, %2};" : "=l"(r) : "f"(lo), "f"(hi));
    return r;
}
__device__ __forceinline__ void unpack2(u64 v, float& lo, float& hi) {
    asm("mov.b64 {%0, %1}, %2;" : "=f"(lo), "=f"(hi) : "l"(v));
}

template <int NT>
__device__ __forceinline__ u64 block_incl_scan(u64 v, u64* sm) {
    int tid = threadIdx.x;
    int lane = tid & 31, wid = tid >> 5;
    u64 x = v;
#pragma unroll
    for (int d = 1; d < 32; d <<= 1) {
        u64 y = __shfl_up_sync(0xffffffffu, x, d);
        if (lane >= d) x += y;
    }
    if (lane == 31) sm[wid] = x;
    __syncthreads();
    if (wid == 0) {
        u64 w = (lane < (NT / 32)) ? sm[lane] : 0ull;
#pragma unroll
        for (int d = 1; d < 32; d <<= 1) {
            u64 y = __shfl_up_sync(0xffffffffu, w, d);
            if (lane >= d) w += y;
        }
        if (lane < (NT / 32)) sm[lane] = w;
    }
    __syncthreads();
    u64 base = wid ? sm[wid - 1] : 0ull;
    u64 r = x + base;
    __syncthreads();
    return r;
}

// ---- P1 tile v4: 32 rows x 256 cols, K=64 ----
// 8 rows x 2 col-pairs per thread: per k per warp = 2 W LDS.64 + 4 L LDS.128
// (broadcast) + 16 FFMA2. Halves W crossbar traffic vs v1; fma-pipe bound.
__device__ __forceinline__ void p1_tile(int tile, const float* __restrict__ loc_table,
                                        const float* __restrict__ W) {
    __shared__ __align__(16) float Wsm[32 * 256];   // 32 KB k-chunk of W
    __shared__ __align__(16) u64 Ldup[64 * 32];     // 16 KB [k][row] dup pairs
    int tid = threadIdx.x;
    int lane = tid & 31;
    int w = tid >> 5;
    int rowbase = tile * 32;
    // stage L transposed + duplicated (all 64 k)
    for (int idx = tid; idx < 32 * 64; idx += 256) {
        int row = idx >> 6, col = idx & 63;
        float v = loc_table[(size_t)rowbase * 64 + row * 64 + col];
        Ldup[col * 32 + row] = pack2(v, v);
    }
    const int g8 = (w & 3) * 8;      // row group: rows g8..g8+7
    const int h = w >> 2;            // col half: cols h*128..h*128+127

    u64 acc[2][8];
#pragma unroll
    for (int p = 0; p < 2; p++)
#pragma unroll
        for (int r = 0; r < 8; r++) acc[p][r] = 0ull;

    for (int kc = 0; kc < 2; kc++) {
        __syncthreads();
        for (int idx = tid; idx < 32 * 256; idx += 256)
            Wsm[idx] = W[kc * 32 * 256 + idx];
        __syncthreads();
#pragma unroll 4
        for (int k = 0; k < 32; k++) {
            const u64* wrow =
                reinterpret_cast<const u64*>(&Wsm[k * 256 + h * 128]);
            u64 wv0 = wrow[lane];        // cols h*128 + 2lane, 2lane+1
            u64 wv1 = wrow[32 + lane];   // cols h*128 + 64 + 2lane, ...
            int kk = kc * 32 + k;
            const ulonglong2* lp =
                reinterpret_cast<const ulonglong2*>(&Ldup[kk * 32 + g8]);
            ulonglong2 l01 = lp[0];
            ulonglong2 l23 = lp[1];
            ulonglong2 l45 = lp[2];
            ulonglong2 l67 = lp[3];
            u64 lv[8] = {l01.x, l01.y, l23.x, l23.y, l45.x, l45.y, l67.x, l67.y};
#pragma unroll
            for (int r = 0; r < 8; r++) {
                acc[0][r] = ffma2(lv[r], wv0, acc[0][r]);
                acc[1][r] = ffma2(lv[r], wv1, acc[1][r]);
            }
        }
    }
#pragma unroll
    for (int r = 0; r < 8; r++) {
        size_t row = rowbase + g8 + r;
        float2* o = reinterpret_cast<float2*>(&g_P1[row * OUTC + h * 128]);
        float lo, hi;
        unpack2(acc[0][r], lo, hi);
        o[lane] = make_float2(lo, hi);
        unpack2(acc[1][r], lo, hi);
        o[32 + lane] = make_float2(lo, hi);
    }
}

// ---------------- stage bodies ----------------
__device__ __forceinline__ void hist_body(int b, const int* __restrict__ x,
                                          const int* __restrict__ t) {
    int j = b * 256 + threadIdx.x;
    if (j < NEVT) {
        u32 key = (u32)__ldg(&x[j]) * NTIMES + (u32)__ldg(&t[j]);
        atomicAdd(&g_cntw[key >> 2], 1u << ((key & 3) * 8));
    }
}

__device__ __forceinline__ void p23_body(int r, const float* __restrict__ time_table,
                                         const float* __restrict__ user_table,
                                         const float* __restrict__ W,
                                         const float* __restrict__ b) {
    int c = threadIdx.x;
    float a2 = b[c];
#pragma unroll 8
    for (int k = 0; k < 32; k++)
        a2 += time_table[r * 32 + k] * W[(64 + k) * OUTC + c];
    g_P2b[r * OUTC + c] = a2;
    float a3 = 0.f;
#pragma unroll 8
    for (int k = 0; k < 64; k++)
        a3 += user_table[r * 64 + k] * W[(96 + k) * OUTC + c];
    g_P3[r * OUTC + c] = a3;
}

// single-pass scan + emit, warp-parallel decoupled lookback
__device__ __forceinline__ void scan_emit_body(int b) {
    __shared__ u32 s_w[WPB];
    __shared__ u64 sm2[SCAN_T / 32];
    __shared__ u64 s_bcast;
    int tid = threadIdx.x;
    size_t base = (size_t)b * WPB;
    for (int j = 0; j < WPB / SCAN_T; j++) {
        size_t idx = base + j * SCAN_T + tid;
        s_w[j * SCAN_T + tid] = (idx < NWORDS) ? g_cntw[idx] : 0u;
    }
    __syncthreads();
    int w0 = tid * (WPB / SCAN_T);
    u32 fs = 0, cs = 0;
#pragma unroll
    for (int j = 0; j < WPB / SCAN_T; j++) {
        u32 wv = s_w[w0 + j];
        cs = __dp4a(wv, 0x01010101u, cs);
        fs += __popc(__vcmpne4(wv, 0u) & 0x01010101u);
    }
    u64 mine = ((u64)fs << 24) | cs;
    u64 incl = block_incl_scan<SCAN_T>(mine, sm2);
    u64 excl = incl - mine;
    if (tid == SCAN_T - 1) s_bcast = incl;
    __syncthreads();
    u64 total = s_bcast;
    __syncthreads();
    if (tid < 32) {
        u64 prefix = 0;
        if (b == 0) {
            if (tid == 0)
                atomicExch((unsigned long long*)&g_state[0], (2ull << 62) | total);
        } else {
            if (tid == 0)
                atomicExch((unsigned long long*)&g_state[b], (1ull << 62) | total);
            int wbase = b;
            while (true) {
                int idx = wbase - 32 + tid;
                u64 v;
                if (idx >= 0) {
                    do {
                        v = atomicAdd((unsigned long long*)&g_state[idx], 0ull);
                        if ((v >> 62) == 0) __nanosleep(20);
                    } while ((v >> 62) == 0);
                } else {
                    v = (2ull << 62);
                }
                u32 mask2 = __ballot_sync(0xffffffffu, (v >> 62) == 2);
                u64 contrib = v & AGMASK;
                if (mask2) {
                    int firstlane = 31 - __clz(mask2);
                    if (tid < firstlane) contrib = 0;
                }
#pragma unroll
                for (int d = 16; d; d >>= 1)
                    contrib += __shfl_down_sync(0xffffffffu, contrib, d);
                contrib = __shfl_sync(0xffffffffu, contrib, 0);
                prefix += contrib;
                if (mask2) break;
                wbase -= 32;
            }
            if (tid == 0)
                atomicExch((unsigned long long*)&g_state[b],
                           (2ull << 62) | (prefix + total));
        }
        if (tid == 0) {
            if (b == NSBLK - 1)
                g_numrows = (u32)(((prefix + total) >> 24) & 0xFFFFFFu);
            s_bcast = prefix;
        }
    }
    __syncthreads();
    u64 run = s_bcast + excl;
    u32 frun = (u32)((run >> 24) & 0xFFFFFFu);
    u32 crun = (u32)(run & 0xFFFFFFull);
#pragma unroll
    for (int j = 0; j < WPB / SCAN_T; j++) {
        u32 wv = s_w[w0 + j];
        if (!wv) continue;
#pragma unroll
        for (int lane = 0; lane < 4; lane++) {
            u32 c = (wv >> (lane * 8)) & 0xffu;
            if (c) {
                u32 key = (u32)((base + w0 + j) * 4 + lane);
                g_key[frun] = key;
                g_count[frun] = c;
                g_cursor[frun] = crun;
                g_rowid[key] = frun;
                frun++;
                crun += c;
            }
        }
    }
}

__device__ __forceinline__ void scatter_body(int b, const int* __restrict__ x,
                                             const int* __restrict__ t,
                                             const int* __restrict__ u) {
    int j = b * 256 + threadIdx.x;
    if (j < NEVT) {
        u32 key = (u32)__ldg(&x[j]) * NTIMES + (u32)__ldg(&t[j]);
        u32 row = g_rowid[key];
        u32 pos = atomicAdd(&g_cursor[row], 1u);
        g_evtu[pos] = (u32)__ldg(&u[j]);
    }
}

// ---------------- kernels ----------------
__global__ void __launch_bounds__(256) k1_p1_p23_hist(const int* __restrict__ x,
                                                      const int* __restrict__ t,
                                                      const float* __restrict__ loc,
                                                      const float* __restrict__ time_table,
                                                      const float* __restrict__ user_table,
                                                      const float* __restrict__ W,
                                                      const float* __restrict__ b) {
    int bid = blockIdx.x;
    if (bid < T1) p1_tile(bid, loc, W);
    else if (bid < T1 + NTIMES) p23_body(bid - T1, time_table, user_table, W, b);
    else hist_body(bid - T1 - NTIMES, x, t);
}

__global__ void __launch_bounds__(256) k2_scan_p1(const float* __restrict__ loc,
                                                  const float* __restrict__ W) {
    int bid = blockIdx.x;
    if (bid < NSBLK) scan_emit_body(bid);
    else p1_tile(bid - NSBLK + T1, loc, W);
}

__global__ void __launch_bounds__(256) k3_p1_scatter(const int* __restrict__ x,
                                                     const int* __restrict__ t,
                                                     const int* __restrict__ u,
                                                     const float* __restrict__ loc,
                                                     const float* __restrict__ W) {
    int bid = blockIdx.x;
    if (bid < T3) p1_tile(bid + T1 + T2, loc, W);
    else scatter_body(bid - T3, x, t, u);
}

// final: warp-cooperative rows + cleanup tail riding the same grid
__global__ void __launch_bounds__(256) k4_final(float* __restrict__ out,
                                                const int* __restrict__ x,
                                                const int* __restrict__ t) {
    int bid = blockIdx.x;
    int tid = threadIdx.x;
    if (bid >= FB) {
        int j = (bid - FB) * 256 + tid;
        if (j < NEVT) {
            u32 key = (u32)__ldg(&x[j]) * NTIMES + (u32)__ldg(&t[j]);
            g_cntw[key >> 2] = 0u;
        }
        if (bid == FB) {
            for (int i = tid; i < NSBLK; i += 256) g_state[i] = 0ull;
        }
        return;
    }

    const u32 K = g_numrows;
    const int lane = tid & 31;
    const int w = tid >> 5;
    const int rowbase = bid * RPB + w * 32;

    int i = rowbase + lane;
    u32 cnt = 0, p1i = 0, p2i = 0, ufi = 0, sti = 0;
    float inv = 0.f;
    if (i < (int)K) {
        u32 key = g_key[i];
        cnt = g_count[i];
        u32 end = g_cursor[i];
        sti = end - cnt;
        u32 xu = key / NTIMES;
        u32 tu = key - xu * NTIMES;
        p1i = xu * 64;
        p2i = tu * 64;
        inv = 1.0f / (float)cnt;
        ufi = g_evtu[sti] * 64;
    }

    const float4* __restrict__ P1f = reinterpret_cast<const float4*>(g_P1);
    const float4* __restrict__ P2f = reinterpret_cast<const float4*>(g_P2b);
    const float4* __restrict__ P3f = reinterpret_cast<const float4*>(g_P3);
    float4* o = reinterpret_cast<float4*>(out);

#pragma unroll 2
    for (int r = 0; r < 32; r++) {
        int row = rowbase + r;
        if (row >= NEVT) break;
        u32 c = __shfl_sync(0xffffffffu, cnt, r);
        u32 ob = (u32)row * 64 + lane;
        if (c == 0) {
            float4 z = make_float4(0.f, 0.f, 0.f, 0.f);
            __stcs(&o[ob], z);
            __stcs(&o[ob + 32], z);
            continue;
        }
        u32 p1 = __shfl_sync(0xffffffffu, p1i, r);
        u32 p2 = __shfl_sync(0xffffffffu, p2i, r);
        u32 uf = __shfl_sync(0xffffffffu, ufi, r);
        float iv = __shfl_sync(0xffffffffu, inv, r);

        float4 a0 = P1f[(size_t)p1 + lane];
        float4 a1 = P1f[(size_t)p1 + 32 + lane];
        float4 b0 = P2f[p2 + lane];
        float4 b1 = P2f[p2 + 32 + lane];
        float4 s0 = P3f[uf + lane];
        float4 s1 = P3f[uf + 32 + lane];

        if (c > 1) {
            u32 st = __shfl_sync(0xffffffffu, sti, r);
            for (u32 e = 1; e < c; e++) {
                u32 uu = g_evtu[st + e] * 64;
                float4 q0 = P3f[uu + lane];
                float4 q1 = P3f[uu + 32 + lane];
                s0.x += q0.x; s0.y += q0.y; s0.z += q0.z; s0.w += q0.w;
                s1.x += q1.x; s1.y += q1.y; s1.z += q1.z; s1.w += q1.w;
            }
        }

        float4 v0 = make_float4(a0.x + b0.x + s0.x * iv, a0.y + b0.y + s0.y * iv,
                                a0.z + b0.z + s0.z * iv, a0.w + b0.w + s0.w * iv);
        float4 v1 = make_float4(a1.x + b1.x + s1.x * iv, a1.y + b1.y + s1.y * iv,
                                a1.z + b1.z + s1.z * iv, a1.w + b1.w + s1.w * iv);
        __stcs(&o[ob], v0);
        __stcs(&o[ob + 32], v1);
    }
}

// ---------------- launch ----------------
extern "C" void kernel_launch(void* const* d_in, const int* in_sizes, int n_in,
                              void* d_out, int out_size) {
    const int* x = (const int*)d_in[0];
    const int* t = (const int*)d_in[1];
    const int* u = (const int*)d_in[2];
    const float* loc_table = (const float*)d_in[3];
    const float* time_table = (const float*)d_in[4];
    const float* user_table = (const float*)d_in[5];
    const float* W = (const float*)d_in[6];
    const float* b = (const float*)d_in[7];
    float* out = (float*)d_out;

    k1_p1_p23_hist<<<T1 + NTIMES + HB, 256>>>(x, t, loc_table, time_table,
                                              user_table, W, b);
    k2_scan_p1<<<NSBLK + T2, 256>>>(loc_table, W);
    k3_p1_scatter<<<T3 + HB, 256>>>(x, t, u, loc_table, W);
    k4_final<<<FB + CB, 256>>>(out, x, t);
}

// round 16
// speedup vs baseline: 1.1124x; 1.1124x over previous
#include <cuda_runtime.h>

#define NEVT    400000
#define NLOCS   100000
#define NTIMES  168
#define NKEYS   (NLOCS * NTIMES)          /* 16,800,000 */
#define NWORDS  (NKEYS / 4)               /* 4,200,000 packed counter words */
#define OUTC    256
#define SCAN_T  256
#define WPB     4096
#define NSBLK   ((NWORDS + WPB - 1) / WPB)/* 1026 */
#define HB      ((NEVT + 255) / 256)      /* 1563 */
#define NTILES  (NLOCS / 32)              /* 3125 P1 tiles (32 rows) */
#define RPB     256                       /* rows per k4 block (8 warps x 32) */
#define FB      ((NEVT + RPB - 1) / RPB)  /* 1563 final blocks */
#define CB      ((NEVT + 255) / 256)      /* cleanup blocks (ride k4 grid) */
#define AGMASK  0x3FFFFFFFFFFFFFFFull

typedef unsigned int u32;
typedef unsigned long long u64;

// ---------------- scratch ----------------
__device__ u32 g_cntw[NWORDS];
__device__ u32 g_rowid[NKEYS];
__device__ u64 g_state[NSBLK];
__device__ u32 g_numrows;
__device__ u32 g_key[NEVT];
__device__ u32 g_count[NEVT];
__device__ u32 g_cursor[NEVT];
__device__ u32 g_evtu[NEVT];
__device__ __align__(16) float g_P1[(size_t)NLOCS * OUTC];
__device__ __align__(16) float g_P2b[NTIMES * OUTC];
__device__ __align__(16) float g_P3[NTIMES * OUTC];

// ---------------- helpers ----------------
__device__ __forceinline__ u64 ffma2(u64 a, u64 b, u64 c) {
    u64 d;
    asm("fma.rn.f32x2 %0, %1, %2, %3;" : "=l"(d) : "l"(a), "l"(b), "l"(c));
    return d;
}
__device__ __forceinline__ u64 pack2(float lo, float hi) {
    u64 r;
    asm("mov.b64 %0, {%1, %2};" : "=l"(r) : "f"(lo), "f"(hi));
    return r;
}
__device__ __forceinline__ void unpack2(u64 v, float& lo, float& hi) {
    asm("mov.b64 {%0, %1}, %2;" : "=f"(lo), "=f"(hi) : "l"(v));
}

template <int NT>
__device__ __forceinline__ u64 block_incl_scan(u64 v, u64* sm) {
    int tid = threadIdx.x;
    int lane = tid & 31, wid = tid >> 5;
    u64 x = v;
#pragma unroll
    for (int d = 1; d < 32; d <<= 1) {
        u64 y = __shfl_up_sync(0xffffffffu, x, d);
        if (lane >= d) x += y;
    }
    if (lane == 31) sm[wid] = x;
    __syncthreads();
    if (wid == 0) {
        u64 w = (lane < (NT / 32)) ? sm[lane] : 0ull;
#pragma unroll
        for (int d = 1; d < 32; d <<= 1) {
            u64 y = __shfl_up_sync(0xffffffffu, w, d);
            if (lane >= d) w += y;
        }
        if (lane < (NT / 32)) sm[lane] = w;
    }
    __syncthreads();
    u64 base = wid ? sm[wid - 1] : 0ull;
    u64 r = x + base;
    __syncthreads();
    return r;
}

// ---- P1 tile v1 (best measured): 32 rows x 256 cols, K=64, FFMA2 ----
__device__ __forceinline__ void p1_tile(int tile, const float* __restrict__ loc_table,
                                        const float* __restrict__ W) {
    __shared__ __align__(16) float Wsm[32 * 256];   // 32 KB
    __shared__ __align__(16) float Lsm[32 * 64];    // 8 KB
    int tid = threadIdx.x;
    int rowbase = tile * 32;
    for (int idx = tid; idx < 32 * 64; idx += 256)
        Lsm[idx] = loc_table[(size_t)rowbase * 64 + idx];
    int cp = tid & 31;
    int w = tid >> 5;    // warp -> rows w*4 .. w*4+3
    u64 acc[4][4];
#pragma unroll
    for (int g = 0; g < 4; g++)
#pragma unroll
        for (int r = 0; r < 4; r++) acc[g][r] = 0ull;

    for (int kc = 0; kc < 2; kc++) {
        __syncthreads();
        for (int idx = tid; idx < 32 * 256; idx += 256)
            Wsm[idx] = W[kc * 32 * 256 + idx];
        __syncthreads();
#pragma unroll 4
        for (int k = 0; k < 32; k++) {
            const u64* wrow = reinterpret_cast<const u64*>(&Wsm[k * 256]);
            u64 wv0 = wrow[cp];
            u64 wv1 = wrow[32 + cp];
            u64 wv2 = wrow[64 + cp];
            u64 wv3 = wrow[96 + cp];
            int kk = kc * 32 + k;
#pragma unroll
            for (int r = 0; r < 4; r++) {
                float l = Lsm[(w * 4 + r) * 64 + kk];
                u64 ll = pack2(l, l);
                acc[0][r] = ffma2(ll, wv0, acc[0][r]);
                acc[1][r] = ffma2(ll, wv1, acc[1][r]);
                acc[2][r] = ffma2(ll, wv2, acc[2][r]);
                acc[3][r] = ffma2(ll, wv3, acc[3][r]);
            }
        }
    }
#pragma unroll
    for (int r = 0; r < 4; r++) {
        size_t row = rowbase + w * 4 + r;
        float2* o = reinterpret_cast<float2*>(&g_P1[row * OUTC]);
#pragma unroll
        for (int g = 0; g < 4; g++) {
            float lo, hi;
            unpack2(acc[g][r], lo, hi);
            o[g * 32 + cp] = make_float2(lo, hi);
        }
    }
}

// ---------------- stage bodies ----------------
__device__ __forceinline__ void hist_body(int b, const int* __restrict__ x,
                                          const int* __restrict__ t) {
    int j = b * 256 + threadIdx.x;
    if (j < NEVT) {
        u32 key = (u32)__ldg(&x[j]) * NTIMES + (u32)__ldg(&t[j]);
        atomicAdd(&g_cntw[key >> 2], 1u << ((key & 3) * 8));
    }
}

__device__ __forceinline__ void p23_body(int r, const float* __restrict__ time_table,
                                         const float* __restrict__ user_table,
                                         const float* __restrict__ W,
                                         const float* __restrict__ b) {
    int c = threadIdx.x;
    float a2 = b[c];
#pragma unroll 8
    for (int k = 0; k < 32; k++)
        a2 += time_table[r * 32 + k] * W[(64 + k) * OUTC + c];
    g_P2b[r * OUTC + c] = a2;
    float a3 = 0.f;
#pragma unroll 8
    for (int k = 0; k < 64; k++)
        a3 += user_table[r * 64 + k] * W[(96 + k) * OUTC + c];
    g_P3[r * OUTC + c] = a3;
}

// single-pass scan + emit, warp-parallel decoupled lookback
__device__ __forceinline__ void scan_emit_body(int b) {
    __shared__ u32 s_w[WPB];
    __shared__ u64 sm2[SCAN_T / 32];
    __shared__ u64 s_bcast;
    int tid = threadIdx.x;
    size_t base = (size_t)b * WPB;
    for (int j = 0; j < WPB / SCAN_T; j++) {
        size_t idx = base + j * SCAN_T + tid;
        s_w[j * SCAN_T + tid] = (idx < NWORDS) ? g_cntw[idx] : 0u;
    }
    __syncthreads();
    int w0 = tid * (WPB / SCAN_T);
    u32 fs = 0, cs = 0;
#pragma unroll
    for (int j = 0; j < WPB / SCAN_T; j++) {
        u32 wv = s_w[w0 + j];
        cs = __dp4a(wv, 0x01010101u, cs);
        fs += __popc(__vcmpne4(wv, 0u) & 0x01010101u);
    }
    u64 mine = ((u64)fs << 24) | cs;
    u64 incl = block_incl_scan<SCAN_T>(mine, sm2);
    u64 excl = incl - mine;
    if (tid == SCAN_T - 1) s_bcast = incl;
    __syncthreads();
    u64 total = s_bcast;
    __syncthreads();
    if (tid < 32) {
        u64 prefix = 0;
        if (b == 0) {
            if (tid == 0)
                atomicExch((unsigned long long*)&g_state[0], (2ull << 62) | total);
        } else {
            if (tid == 0)
                atomicExch((unsigned long long*)&g_state[b], (1ull << 62) | total);
            int wbase = b;
            while (true) {
                int idx = wbase - 32 + tid;
                u64 v;
                if (idx >= 0) {
                    do {
                        v = atomicAdd((unsigned long long*)&g_state[idx], 0ull);
                        if ((v >> 62) == 0) __nanosleep(20);
                    } while ((v >> 62) == 0);
                } else {
                    v = (2ull << 62);
                }
                u32 mask2 = __ballot_sync(0xffffffffu, (v >> 62) == 2);
                u64 contrib = v & AGMASK;
                if (mask2) {
                    int firstlane = 31 - __clz(mask2);
                    if (tid < firstlane) contrib = 0;
                }
#pragma unroll
                for (int d = 16; d; d >>= 1)
                    contrib += __shfl_down_sync(0xffffffffu, contrib, d);
                contrib = __shfl_sync(0xffffffffu, contrib, 0);
                prefix += contrib;
                if (mask2) break;
                wbase -= 32;
            }
            if (tid == 0)
                atomicExch((unsigned long long*)&g_state[b],
                           (2ull << 62) | (prefix + total));
        }
        if (tid == 0) {
            if (b == NSBLK - 1)
                g_numrows = (u32)(((prefix + total) >> 24) & 0xFFFFFFu);
            s_bcast = prefix;
        }
    }
    __syncthreads();
    u64 run = s_bcast + excl;
    u32 frun = (u32)((run >> 24) & 0xFFFFFFu);
    u32 crun = (u32)(run & 0xFFFFFFull);
#pragma unroll
    for (int j = 0; j < WPB / SCAN_T; j++) {
        u32 wv = s_w[w0 + j];
        if (!wv) continue;
#pragma unroll
        for (int lane = 0; lane < 4; lane++) {
            u32 c = (wv >> (lane * 8)) & 0xffu;
            if (c) {
                u32 key = (u32)((base + w0 + j) * 4 + lane);
                g_key[frun] = key;
                g_count[frun] = c;
                g_cursor[frun] = crun;
                g_rowid[key] = frun;
                frun++;
                crun += c;
            }
        }
    }
}

// ---------------- kernels ----------------
// P1 on its own graph branch: pure tile kernel, no internal joins
__global__ void __launch_bounds__(256) k_p1_all(const float* __restrict__ loc,
                                                const float* __restrict__ W) {
    p1_tile(blockIdx.x, loc, W);
}

__global__ void __launch_bounds__(256) k1_p23_hist(const int* __restrict__ x,
                                                   const int* __restrict__ t,
                                                   const float* __restrict__ time_table,
                                                   const float* __restrict__ user_table,
                                                   const float* __restrict__ W,
                                                   const float* __restrict__ b) {
    int bid = blockIdx.x;
    if (bid < NTIMES) p23_body(bid, time_table, user_table, W, b);
    else hist_body(bid - NTIMES, x, t);
}

__global__ void __launch_bounds__(256) k2_scan(void) {
    scan_emit_body(blockIdx.x);
}

__global__ void __launch_bounds__(256) k3_scatter(const int* __restrict__ x,
                                                  const int* __restrict__ t,
                                                  const int* __restrict__ u) {
    int j = blockIdx.x * 256 + threadIdx.x;
    if (j < NEVT) {
        u32 key = (u32)__ldg(&x[j]) * NTIMES + (u32)__ldg(&t[j]);
        u32 row = g_rowid[key];
        u32 pos = atomicAdd(&g_cursor[row], 1u);
        g_evtu[pos] = (u32)__ldg(&u[j]);
    }
}

// final: warp-cooperative rows + cleanup tail riding the same grid (R11 verbatim)
__global__ void __launch_bounds__(256) k4_final(float* __restrict__ out,
                                                const int* __restrict__ x,
                                                const int* __restrict__ t) {
    int bid = blockIdx.x;
    int tid = threadIdx.x;
    if (bid >= FB) {
        int j = (bid - FB) * 256 + tid;
        if (j < NEVT) {
            u32 key = (u32)__ldg(&x[j]) * NTIMES + (u32)__ldg(&t[j]);
            g_cntw[key >> 2] = 0u;
        }
        if (bid == FB) {
            for (int i = tid; i < NSBLK; i += 256) g_state[i] = 0ull;
        }
        return;
    }

    const u32 K = g_numrows;
    const int lane = tid & 31;
    const int w = tid >> 5;
    const int rowbase = bid * RPB + w * 32;

    int i = rowbase + lane;
    u32 cnt = 0, p1i = 0, p2i = 0, ufi = 0, sti = 0;
    float inv = 0.f;
    if (i < (int)K) {
        u32 key = g_key[i];
        cnt = g_count[i];
        u32 end = g_cursor[i];
        sti = end - cnt;
        u32 xu = key / NTIMES;
        u32 tu = key - xu * NTIMES;
        p1i = xu * 64;
        p2i = tu * 64;
        inv = 1.0f / (float)cnt;
        ufi = g_evtu[sti] * 64;
    }

    const float4* __restrict__ P1f = reinterpret_cast<const float4*>(g_P1);
    const float4* __restrict__ P2f = reinterpret_cast<const float4*>(g_P2b);
    const float4* __restrict__ P3f = reinterpret_cast<const float4*>(g_P3);
    float4* o = reinterpret_cast<float4*>(out);

#pragma unroll 2
    for (int r = 0; r < 32; r++) {
        int row = rowbase + r;
        if (row >= NEVT) break;
        u32 c = __shfl_sync(0xffffffffu, cnt, r);
        u32 ob = (u32)row * 64 + lane;
        if (c == 0) {
            float4 z = make_float4(0.f, 0.f, 0.f, 0.f);
            __stcs(&o[ob], z);
            __stcs(&o[ob + 32], z);
            continue;
        }
        u32 p1 = __shfl_sync(0xffffffffu, p1i, r);
        u32 p2 = __shfl_sync(0xffffffffu, p2i, r);
        u32 uf = __shfl_sync(0xffffffffu, ufi, r);
        float iv = __shfl_sync(0xffffffffu, inv, r);

        float4 a0 = P1f[(size_t)p1 + lane];
        float4 a1 = P1f[(size_t)p1 + 32 + lane];
        float4 b0 = P2f[p2 + lane];
        float4 b1 = P2f[p2 + 32 + lane];
        float4 s0 = P3f[uf + lane];
        float4 s1 = P3f[uf + 32 + lane];

        if (c > 1) {
            u32 st = __shfl_sync(0xffffffffu, sti, r);
            for (u32 e = 1; e < c; e++) {
                u32 uu = g_evtu[st + e] * 64;
                float4 q0 = P3f[uu + lane];
                float4 q1 = P3f[uu + 32 + lane];
                s0.x += q0.x; s0.y += q0.y; s0.z += q0.z; s0.w += q0.w;
                s1.x += q1.x; s1.y += q1.y; s1.z += q1.z; s1.w += q1.w;
            }
        }

        float4 v0 = make_float4(a0.x + b0.x + s0.x * iv, a0.y + b0.y + s0.y * iv,
                                a0.z + b0.z + s0.z * iv, a0.w + b0.w + s0.w * iv);
        float4 v1 = make_float4(a1.x + b1.x + s1.x * iv, a1.y + b1.y + s1.y * iv,
                                a1.z + b1.z + s1.z * iv, a1.w + b1.w + s1.w * iv);
        __stcs(&o[ob], v0);
        __stcs(&o[ob + 32], v1);
    }
}

// ---------------- launch: fork-join graph (P1 on side branch) ----------------
extern "C" void kernel_launch(void* const* d_in, const int* in_sizes, int n_in,
                              void* d_out, int out_size) {
    const int* x = (const int*)d_in[0];
    const int* t = (const int*)d_in[1];
    const int* u = (const int*)d_in[2];
    const float* loc_table = (const float*)d_in[3];
    const float* time_table = (const float*)d_in[4];
    const float* user_table = (const float*)d_in[5];
    const float* W = (const float*)d_in[6];
    const float* b = (const float*)d_in[7];
    float* out = (float*)d_out;

    static cudaStream_t sB = nullptr;
    static cudaEvent_t eFork = nullptr, eJoin = nullptr;
    if (sB == nullptr) {
        cudaStreamCreateWithFlags(&sB, cudaStreamNonBlocking);
        cudaEventCreateWithFlags(&eFork, cudaEventDisableTiming);
        cudaEventCreateWithFlags(&eJoin, cudaEventDisableTiming);
    }

    // fork: side branch computes P1 while main branch runs hist -> scan -> scatter
    cudaEventRecord(eFork, 0);
    cudaStreamWaitEvent(sB, eFork, 0);
    k_p1_all<<<NTILES, 256, 0, sB>>>(loc_table, W);

    k1_p23_hist<<<NTIMES + HB, 256>>>(x, t, time_table, user_table, W, b);
    k2_scan<<<NSBLK, 256>>>();
    k3_scatter<<<HB, 256>>>(x, t, u);

    // join: k4 needs both branches
    cudaEventRecord(eJoin, sB);
    cudaStreamWaitEvent(0, eJoin, 0);
    k4_final<<<FB + CB, 256>>>(out, x, t);
}